// round 13
// baseline (speedup 1.0000x reference)
#include <cuda_runtime.h>
#include <cuda_bf16.h>

#define BATCH 4096
#define TT    1024
#define NVOC  32000
#define HID   16

typedef unsigned long long ull;

// Scratch (device globals: allocation-free rule)
__device__ float g_xtab[NVOC * HID];   // 2MB: precomputed x-projection per token
__device__ float g_hfin[BATCH * HID];  // 256KB: final hidden states

// ---- packed f32x2 helpers on 64-bit registers ----
__device__ __forceinline__ ull ffma2(ull a, ull b, ull c) {
    ull d;
    asm("fma.rn.f32x2 %0, %1, %2, %3;" : "=l"(d) : "l"(a), "l"(b), "l"(c));
    return d;
}
__device__ __forceinline__ ull add2(ull a, ull b) {
    ull d;
    asm("add.rn.f32x2 %0, %1, %2;" : "=l"(d) : "l"(a), "l"(b));
    return d;
}
__device__ __forceinline__ ull pk(float lo, float hi) {
    ull r;
    asm("mov.b64 %0, {%1, %2};" : "=l"(r) : "f"(lo), "f"(hi));
    return r;
}
__device__ __forceinline__ float hsum2(ull a) {   // lo + hi
    float lo, hi;
    asm("mov.b64 {%0, %1}, %2;" : "=f"(lo), "=f"(hi) : "l"(a));
    return lo + hi;
}
__device__ __forceinline__ float tanhx(float x) {
    float r;
    asm("tanh.approx.f32 %0, %1;" : "=f"(r) : "f"(x));
    return r;
}
__device__ __forceinline__ unsigned smem_u32(const void* p) {
    unsigned a;
    asm("{ .reg .u64 t; cvta.to.shared.u64 t, %1; cvt.u32.u64 %0, t; }"
        : "=r"(a) : "l"(p));
    return a;
}

// shim: steers the ncu capture window (position 4) onto rnn_scan
__global__ void shim_kernel(int* p) { if (p) *p = 0; }

// ---------------------------------------------------------------------------
// Kernel 1: xtab[v][o] = Wx_b[o] + sum_h embed[v][h] * Wx_w[o][h]
// ---------------------------------------------------------------------------
__global__ void build_xtab(const float* __restrict__ embed,
                           const float* __restrict__ Wxw,
                           const float* __restrict__ Wxb) {
    int tid = blockIdx.x * blockDim.x + threadIdx.x;
    if (tid >= NVOC * HID) return;
    int v = tid >> 4;
    int o = tid & 15;
    const float4* er = (const float4*)(embed + v * HID);
    const float4* wr = (const float4*)(Wxw + o * HID);
    float s = Wxb[o];
#pragma unroll
    for (int i = 0; i < 4; i++) {
        float4 e = __ldg(&er[i]);
        float4 w = __ldg(&wr[i]);
        s += e.x * w.x + e.y * w.y + e.z * w.z + e.w * w.w;
    }
    g_xtab[tid] = s;
}

// ---------------------------------------------------------------------------
// Kernel 2 R12: recurrence with 2 batches/warp, 16 lanes/batch, 1 h/lane.
// 2048 warps (3.46/SMSP) so the ~100cyc recurrent chain hides ACROSS warps
// (at 512 warps it was fully exposed: ~225cyc/step). Per lane per step:
// 4 broadcast LDS + 8 FFMA2 + tanh + 1 STS.b32 + syncwarp (~20 instr).
// SMEM rows [bl*16+h]: STS banks all distinct; LDS broadcast conflict-free.
// Final h stays in-register -> coalesced 128B/warp store to g_hfin.
// ---------------------------------------------------------------------------
__global__ void __launch_bounds__(128) rnn_scan(const int* __restrict__ seq,
                                                const float* __restrict__ Wh) {
    __shared__ float hbuf[4][2][32];              // [warp][pingpong][2x16 h]
    const int lane = threadIdx.x & 31;
    const int wid  = threadIdx.x >> 5;            // 0..3
    const int warp = blockIdx.x * 4 + wid;        // 0..2047
    const int bl   = lane >> 4;                   // 0..1: which batch
    const int hidx = lane & 15;                   // which h component

    // h0 = 0
    hbuf[wid][0][lane] = 0.f;

    const unsigned sb0 = smem_u32(&hbuf[wid][0][0]) + bl * 64;   // bytes
    const unsigned sb1 = smem_u32(&hbuf[wid][1][0]) + bl * 64;

    // Wh row for my output: wh[q] = (Wh[hidx][2q], Wh[hidx][2q+1])
    ull wh[8];
    {
        const float4* r = (const float4*)(Wh + hidx * HID);
#pragma unroll
        for (int j = 0; j < 4; j++) {
            float4 t = __ldg(&r[j]);
            wh[2 * j]     = pk(t.x, t.y);
            wh[2 * j + 1] = pk(t.z, t.w);
        }
    }

    const int b = warp * 2 + bl;
    const int* myseq = seq + b * TT;

    // Prime rings: tokring[i] = token[i+8], xpring[i] = xproj[i] (scalar)
    int   tokring[8];
    float xpring[8];
#pragma unroll
    for (int i = 0; i < 8; i++) {
        tokring[i] = __ldg(&myseq[i + 8]);
        xpring[i]  = __ldg(&g_xtab[__ldg(&myseq[i]) * HID + hidx]);
    }
    __syncwarp();

    float hv = 0.f;
#pragma unroll 8
    for (int t = 0; t < TT; t++) {
        const int slot = t & 7;
        float cur = xpring[slot];                  // xproj for step t
        int tok = tokring[slot];                   // token for t+8 (arrived)
        xpring[slot] = __ldg(&g_xtab[tok * HID + hidx]);
        int tn = t + 16; if (tn > TT - 1) tn = TT - 1;
        tokring[slot] = __ldg(&myseq[tn]);

        const unsigned rbase = (t & 1) ? sb1 : sb0;
        const unsigned wbase = (t & 1) ? sb0 : sb1;

        // read my batch's full h[16] as 8 packed pairs (broadcast LDS)
        ull hp[8];
        asm volatile("ld.shared.v2.b64 {%0,%1},[%2];"
                     : "=l"(hp[0]), "=l"(hp[1]) : "r"(rbase) : "memory");
        asm volatile("ld.shared.v2.b64 {%0,%1},[%2];"
                     : "=l"(hp[2]), "=l"(hp[3]) : "r"(rbase + 16) : "memory");
        asm volatile("ld.shared.v2.b64 {%0,%1},[%2];"
                     : "=l"(hp[4]), "=l"(hp[5]) : "r"(rbase + 32) : "memory");
        asm volatile("ld.shared.v2.b64 {%0,%1},[%2];"
                     : "=l"(hp[6]), "=l"(hp[7]) : "r"(rbase + 48) : "memory");

        // one output: two 4-deep FFMA2 chains over 16 h, xproj folded in
        ull aA = ffma2(wh[0], hp[0], pk(cur, 0.f));
        ull aB = ffma2(wh[4], hp[4], 0ull);
#pragma unroll
        for (int q = 1; q < 4; q++) {
            aA = ffma2(wh[q], hp[q], aA);
            aB = ffma2(wh[q + 4], hp[q + 4], aB);
        }
        hv = tanhx(hsum2(add2(aA, aB)));

        asm volatile("st.shared.f32 [%0], %1;"
                     :: "r"(wbase + hidx * 4), "f"(hv) : "memory");
        __syncwarp();
    }

    // final h is in-register; 128B/warp coalesced store
    g_hfin[b * HID + hidx] = hv;
}

// ---------------------------------------------------------------------------
// Kernel 3 (unchanged, measured 128us ~= write wall): v-packed epilogue-free,
// duplicated-pair SMEM staging, direct STG.128. Block = 128-v x 256 batches.
// ---------------------------------------------------------------------------
#define OB_BATCH 256
__global__ void __launch_bounds__(128) out_proj(const float* __restrict__ outw,
                                                const float* __restrict__ outb,
                                                float* __restrict__ out) {
    __shared__ ull s_h[OB_BATCH * 16];          // duplicated h pairs, 32KB
    const int tid  = threadIdx.x;
    const int lane = tid & 31;
    const int wid  = tid >> 5;                  // 0..3
    const int vgrp = blockIdx.x % 250;
    const int bgrp = blockIdx.x / 250;          // 0..15
    const int v0 = vgrp * 128 + lane * 4;
    const int b0 = bgrp * OB_BATCH;

    {
        const float4* src = (const float4*)(g_hfin + (size_t)b0 * HID);
#pragma unroll 8
        for (int i = tid; i < OB_BATCH * 4; i += 128) {
            float4 t = __ldg(&src[i]);
            ull* d = &s_h[i * 4];
            ull p0 = pk(t.x, t.x), p1 = pk(t.y, t.y);
            ull p2 = pk(t.z, t.z), p3 = pk(t.w, t.w);
            asm volatile("st.shared.v2.b64 [%0],{%1,%2};"
                         :: "r"(smem_u32(d)), "l"(p0), "l"(p1) : "memory");
            asm volatile("st.shared.v2.b64 [%0],{%1,%2};"
                         :: "r"(smem_u32(d + 2)), "l"(p2), "l"(p3) : "memory");
        }
    }

    ull w2[16][2];
    {
        float r[4][16];
#pragma unroll
        for (int i = 0; i < 4; i++) {
            const float4* rr = (const float4*)(outw + (v0 + i) * HID);
#pragma unroll
            for (int j = 0; j < 4; j++) {
                float4 t = __ldg(&rr[j]);
                r[i][4 * j] = t.x; r[i][4 * j + 1] = t.y;
                r[i][4 * j + 2] = t.z; r[i][4 * j + 3] = t.w;
            }
        }
#pragma unroll
        for (int h = 0; h < 16; h++) {
            w2[h][0] = pk(r[0][h], r[1][h]);
            w2[h][1] = pk(r[2][h], r[3][h]);
        }
    }
    float4 ob = __ldg((const float4*)(outb + v0));
    const ull bias01 = pk(ob.x, ob.y);
    const ull bias23 = pk(ob.z, ob.w);
    __syncthreads();

    const int bcnt = OB_BATCH / 4;              // 64 per warp
    unsigned haddr = smem_u32(s_h) + (unsigned)(wid * bcnt) * 128;
    float* dst = out + (size_t)(b0 + wid * bcnt) * NVOC + v0;

#pragma unroll 4
    for (int i = 0; i < bcnt; i++) {
        ull hp[16];
#pragma unroll
        for (int q = 0; q < 8; q++) {
            asm volatile("ld.shared.v2.b64 {%0,%1},[%2];"
                         : "=l"(hp[2 * q]), "=l"(hp[2 * q + 1])
                         : "r"(haddr + 16 * q));
        }

        ull a0A = ffma2(w2[0][0], hp[0], bias01);
        ull a1A = ffma2(w2[0][1], hp[0], bias23);
        ull a0B = ffma2(w2[8][0], hp[8], 0ull);
        ull a1B = ffma2(w2[8][1], hp[8], 0ull);
#pragma unroll
        for (int h = 1; h < 8; h++) {
            a0A = ffma2(w2[h][0], hp[h], a0A);
            a1A = ffma2(w2[h][1], hp[h], a1A);
            a0B = ffma2(w2[h + 8][0], hp[h + 8], a0B);
            a1B = ffma2(w2[h + 8][1], hp[h + 8], a1B);
        }
        ull r01 = add2(a0A, a0B);
        ull r23 = add2(a1A, a1B);

        asm volatile("st.global.cs.v2.b64 [%0],{%1,%2};"
                     :: "l"(dst), "l"(r01), "l"(r23) : "memory");

        haddr += 128;
        dst += NVOC;
    }
}

// ---------------------------------------------------------------------------
extern "C" void kernel_launch(void* const* d_in, const int* in_sizes, int n_in,
                              void* d_out, int out_size) {
    const int*   seq   = (const int*)d_in[0];
    const float* embed = (const float*)d_in[1];
    const float* Wh    = (const float*)d_in[2];
    const float* Wxw   = (const float*)d_in[3];
    const float* Wxb   = (const float*)d_in[4];
    const float* outw  = (const float*)d_in[5];
    const float* outb  = (const float*)d_in[6];
    float* out = (float*)d_out;

    build_xtab<<<(NVOC * HID + 255) / 256, 256>>>(embed, Wxw, Wxb);
    shim_kernel<<<1, 32>>>(nullptr);
    shim_kernel<<<1, 32>>>(nullptr);             // rnn_scan = launch #4
    rnn_scan<<<BATCH / 8, 128>>>(seq, Wh);       // 512 blocks x 4 warps = 2048 warps
    out_proj<<<250 * (BATCH / OB_BATCH), 128>>>(outw, outb, out);
}

// round 15
// speedup vs baseline: 1.8103x; 1.8103x over previous
#include <cuda_runtime.h>
#include <cuda_bf16.h>

#define BATCH 4096
#define TT    1024
#define NVOC  32000
#define HID   16

typedef unsigned long long ull;

// Scratch (device globals: allocation-free rule)
__device__ float g_xtab[NVOC * HID];   // 2MB: precomputed x-projection per token
__device__ float g_hfin[BATCH * HID];  // 256KB: final hidden states

// ---- packed f32x2 helpers on 64-bit registers ----
__device__ __forceinline__ ull ffma2(ull a, ull b, ull c) {
    ull d;
    asm("fma.rn.f32x2 %0, %1, %2, %3;" : "=l"(d) : "l"(a), "l"(b), "l"(c));
    return d;
}
__device__ __forceinline__ ull add2(ull a, ull b) {
    ull d;
    asm("add.rn.f32x2 %0, %1, %2;" : "=l"(d) : "l"(a), "l"(b));
    return d;
}
__device__ __forceinline__ ull pk(float lo, float hi) {
    ull r;
    asm("mov.b64 %0, {%1, %2};" : "=l"(r) : "f"(lo), "f"(hi));
    return r;
}
__device__ __forceinline__ float hsum2(ull a) {   // lo + hi
    float lo, hi;
    asm("mov.b64 {%0, %1}, %2;" : "=f"(lo), "=f"(hi) : "l"(a));
    return lo + hi;
}
__device__ __forceinline__ float tanhx(float x) {
    float r;
    asm("tanh.approx.f32 %0, %1;" : "=f"(r) : "f"(x));
    return r;
}
__device__ __forceinline__ unsigned smem_u32(const void* p) {
    unsigned a;
    asm("{ .reg .u64 t; cvta.to.shared.u64 t, %1; cvt.u32.u64 %0, t; }"
        : "=r"(a) : "l"(p));
    return a;
}

// shim: steers the ncu capture window (position 4) onto rnn_scan
__global__ void shim_kernel(int* p) { if (p) *p = 0; }

// ---------------------------------------------------------------------------
// Kernel 1: xtab[v][o] = Wx_b[o] + sum_h embed[v][h] * Wx_w[o][h]
// ---------------------------------------------------------------------------
__global__ void build_xtab(const float* __restrict__ embed,
                           const float* __restrict__ Wxw,
                           const float* __restrict__ Wxb) {
    int tid = blockIdx.x * blockDim.x + threadIdx.x;
    if (tid >= NVOC * HID) return;
    int v = tid >> 4;
    int o = tid & 15;
    const float4* er = (const float4*)(embed + v * HID);
    const float4* wr = (const float4*)(Wxw + o * HID);
    float s = Wxb[o];
#pragma unroll
    for (int i = 0; i < 4; i++) {
        float4 e = __ldg(&er[i]);
        float4 w = __ldg(&wr[i]);
        s += e.x * w.x + e.y * w.y + e.z * w.z + e.w * w.w;
    }
    g_xtab[tid] = s;
}

// ---------------------------------------------------------------------------
// Kernel 2 R14: 4 batches/warp, 8 lanes/batch, 2 h-outputs/lane.
// 1024 warps (1.73/SMSP): two warps interleave per scheduler so the ~110cyc
// recurrent chain is half-hidden, while per-batch instruction cost stays low
// (~8.75 instr/batch/step vs 12.5 in the failed 2-b/w layout).
// lane = (bl = lane>>3 in 0..3, p = lane&7); lane owns h[2p],h[2p+1].
// SMEM rows stride 16 floats: STS.b64 half-warp phases hit banks 0..31
// exactly (conflict-free); LDS.v2.b64 is quarter-warp broadcast.
// ---------------------------------------------------------------------------
__global__ void __launch_bounds__(128) rnn_scan(const int* __restrict__ seq,
                                                const float* __restrict__ Wh) {
    __shared__ float hbuf[4][2][64];              // [warp][pingpong][4 batches x 16]
    const int lane = threadIdx.x & 31;
    const int wid  = threadIdx.x >> 5;            // 0..3
    const int warp = blockIdx.x * 4 + wid;        // 0..1023
    const int bl   = lane >> 3;                   // 0..3: batch within warp
    const int p    = lane & 7;                    // h-pair index

    // h0 = 0
    hbuf[wid][0][lane]      = 0.f;
    hbuf[wid][0][lane + 32] = 0.f;

    const unsigned sb0 = smem_u32(&hbuf[wid][0][0]) + bl * 64;   // bytes
    const unsigned sb1 = smem_u32(&hbuf[wid][1][0]) + bl * 64;

    // Wh rows 2p and 2p+1, packed f32x2 along h (16 ull, loop-invariant)
    ull wh0[8], wh1[8];
    {
        const float4* r0 = (const float4*)(Wh + (2 * p) * HID);
        const float4* r1 = (const float4*)(Wh + (2 * p + 1) * HID);
#pragma unroll
        for (int j = 0; j < 4; j++) {
            float4 a = __ldg(&r0[j]);
            float4 b = __ldg(&r1[j]);
            wh0[2 * j] = pk(a.x, a.y); wh0[2 * j + 1] = pk(a.z, a.w);
            wh1[2 * j] = pk(b.x, b.y); wh1[2 * j + 1] = pk(b.z, b.w);
        }
    }

    const int b = warp * 4 + bl;
    const int* myseq = seq + b * TT;
    const float2* xt2 = (const float2*)g_xtab;    // [v][8] float2 view

    // Prime rings: tokring[i] = token[i+8], xpring[i] = xproj[i] (my 2 comps)
    int    tokring[8];
    float2 xpring[8];
#pragma unroll
    for (int i = 0; i < 8; i++) {
        tokring[i] = __ldg(&myseq[i + 8]);
        xpring[i]  = __ldg(&xt2[__ldg(&myseq[i]) * 8 + p]);
    }
    __syncwarp();

    float h0 = 0.f, h1 = 0.f;
#pragma unroll 8
    for (int t = 0; t < TT; t++) {
        const int slot = t & 7;
        float2 cur = xpring[slot];                 // xproj for step t
        int tok = tokring[slot];                   // token for t+8 (arrived)
        xpring[slot] = __ldg(&xt2[tok * 8 + p]);   // xproj for t+8
        int tn = t + 16; if (tn > TT - 1) tn = TT - 1;
        tokring[slot] = __ldg(&myseq[tn]);         // token for t+16

        const unsigned rbase = (t & 1) ? sb1 : sb0;
        const unsigned wbase = (t & 1) ? sb0 : sb1;

        // my batch's full h[16] as 8 packed pairs (quarter-warp broadcast LDS)
        ull hp[8];
        asm volatile("ld.shared.v2.b64 {%0,%1},[%2];"
                     : "=l"(hp[0]), "=l"(hp[1]) : "r"(rbase) : "memory");
        asm volatile("ld.shared.v2.b64 {%0,%1},[%2];"
                     : "=l"(hp[2]), "=l"(hp[3]) : "r"(rbase + 16) : "memory");
        asm volatile("ld.shared.v2.b64 {%0,%1},[%2];"
                     : "=l"(hp[4]), "=l"(hp[5]) : "r"(rbase + 32) : "memory");
        asm volatile("ld.shared.v2.b64 {%0,%1},[%2];"
                     : "=l"(hp[6]), "=l"(hp[7]) : "r"(rbase + 48) : "memory");

        // 2 outputs, each two 4-deep FFMA2 chains; xproj folded into chain A
        ull a0A = ffma2(wh0[0], hp[0], pk(cur.x, 0.f));
        ull a1A = ffma2(wh1[0], hp[0], pk(cur.y, 0.f));
        ull a0B = ffma2(wh0[4], hp[4], 0ull);
        ull a1B = ffma2(wh1[4], hp[4], 0ull);
#pragma unroll
        for (int q = 1; q < 4; q++) {
            a0A = ffma2(wh0[q], hp[q], a0A);
            a1A = ffma2(wh1[q], hp[q], a1A);
            a0B = ffma2(wh0[q + 4], hp[q + 4], a0B);
            a1B = ffma2(wh1[q + 4], hp[q + 4], a1B);
        }
        h0 = tanhx(hsum2(add2(a0A, a0B)));
        h1 = tanhx(hsum2(add2(a1A, a1B)));

        ull hpk = pk(h0, h1);
        asm volatile("st.shared.b64 [%0], %1;"
                     :: "r"(wbase + p * 8), "l"(hpk) : "memory");
        __syncwarp();
    }

    // final h in-register; warp writes 4 contiguous batches (256B coalesced)
    *(float2*)(g_hfin + b * HID + 2 * p) = make_float2(h0, h1);
}

// ---------------------------------------------------------------------------
// Kernel 3 (reverted to R7 winner): SMEM-staged h, hsum epilogue, grid 2000.
// Block = (128-v weight tile) x (512 batches); 512x16 f32 h-slice staged via
// float4 LDG into 32KB SMEM; inner loop reads h via broadcast LDS.
// ---------------------------------------------------------------------------
#define OB_BATCH 512
__global__ void __launch_bounds__(128) out_proj(const float* __restrict__ outw,
                                                const float* __restrict__ outb,
                                                float* __restrict__ out) {
    __shared__ float4 s_h[OB_BATCH * 4];        // [batch][4xfloat4] = 32KB
    const int tid  = threadIdx.x;
    const int lane = tid & 31;
    const int wid  = tid >> 5;                  // 0..3
    const int vgrp = blockIdx.x % 250;
    const int bgrp = blockIdx.x / 250;          // 0..7
    const int v0 = vgrp * 128 + lane * 4;
    const int b0 = bgrp * OB_BATCH;

    {
        const float4* src = (const float4*)(g_hfin + (size_t)b0 * HID);
#pragma unroll 4
        for (int i = tid; i < OB_BATCH * 4; i += 128) s_h[i] = __ldg(&src[i]);
    }

    ull w[4][8];
#pragma unroll
    for (int i = 0; i < 4; i++) {
        const float4* r = (const float4*)(outw + (v0 + i) * HID);
#pragma unroll
        for (int j = 0; j < 4; j++) {
            float4 t = __ldg(&r[j]);
            w[i][2 * j]     = pk(t.x, t.y);
            w[i][2 * j + 1] = pk(t.z, t.w);
        }
    }
    float4 ob = __ldg((const float4*)(outb + v0));
    __syncthreads();

    const unsigned hsbase = smem_u32(s_h);
    const int bcnt = OB_BATCH / 4;              // 128 per warp
    const int wb0 = b0 + wid * bcnt;
    unsigned haddr = hsbase + (unsigned)(wid * bcnt) * 64;   // 64B per batch
    float* dst = out + (size_t)wb0 * NVOC + v0;

#pragma unroll 4
    for (int i = 0; i < bcnt; i++) {
        ull hp[8];
        asm volatile("ld.shared.v2.b64 {%0,%1},[%2];"
                     : "=l"(hp[0]), "=l"(hp[1]) : "r"(haddr));
        asm volatile("ld.shared.v2.b64 {%0,%1},[%2];"
                     : "=l"(hp[2]), "=l"(hp[3]) : "r"(haddr + 16));
        asm volatile("ld.shared.v2.b64 {%0,%1},[%2];"
                     : "=l"(hp[4]), "=l"(hp[5]) : "r"(haddr + 32));
        asm volatile("ld.shared.v2.b64 {%0,%1},[%2];"
                     : "=l"(hp[6]), "=l"(hp[7]) : "r"(haddr + 48));

        ull aL0 = ffma2(w[0][0], hp[0], pk(ob.x, 0.f));
        ull aL1 = ffma2(w[1][0], hp[0], pk(ob.y, 0.f));
        ull aL2 = ffma2(w[2][0], hp[0], pk(ob.z, 0.f));
        ull aL3 = ffma2(w[3][0], hp[0], pk(ob.w, 0.f));
        ull aH0 = ffma2(w[0][4], hp[4], 0ull);
        ull aH1 = ffma2(w[1][4], hp[4], 0ull);
        ull aH2 = ffma2(w[2][4], hp[4], 0ull);
        ull aH3 = ffma2(w[3][4], hp[4], 0ull);
#pragma unroll
        for (int q = 1; q < 4; q++) {
            aL0 = ffma2(w[0][q], hp[q], aL0);
            aL1 = ffma2(w[1][q], hp[q], aL1);
            aL2 = ffma2(w[2][q], hp[q], aL2);
            aL3 = ffma2(w[3][q], hp[q], aL3);
            aH0 = ffma2(w[0][q + 4], hp[q + 4], aH0);
            aH1 = ffma2(w[1][q + 4], hp[q + 4], aH1);
            aH2 = ffma2(w[2][q + 4], hp[q + 4], aH2);
            aH3 = ffma2(w[3][q + 4], hp[q + 4], aH3);
        }
        float4 res = make_float4(hsum2(add2(aL0, aH0)), hsum2(add2(aL1, aH1)),
                                 hsum2(add2(aL2, aH2)), hsum2(add2(aL3, aH3)));
        __stcs((float4*)dst, res);

        haddr += 64;
        dst += NVOC;
    }
}

// ---------------------------------------------------------------------------
extern "C" void kernel_launch(void* const* d_in, const int* in_sizes, int n_in,
                              void* d_out, int out_size) {
    const int*   seq   = (const int*)d_in[0];
    const float* embed = (const float*)d_in[1];
    const float* Wh    = (const float*)d_in[2];
    const float* Wxw   = (const float*)d_in[3];
    const float* Wxb   = (const float*)d_in[4];
    const float* outw  = (const float*)d_in[5];
    const float* outb  = (const float*)d_in[6];
    float* out = (float*)d_out;

    build_xtab<<<(NVOC * HID + 255) / 256, 256>>>(embed, Wxw, Wxb);
    shim_kernel<<<1, 32>>>(nullptr);
    shim_kernel<<<1, 32>>>(nullptr);             // rnn_scan = capture position 4
    rnn_scan<<<BATCH / 16, 128>>>(seq, Wh);      // 256 blocks x 4 warps = 1024 warps
    out_proj<<<250 * (BATCH / OB_BATCH), 128>>>(outw, outb, out);  // 2000 blocks
}